// round 9
// baseline (speedup 1.0000x reference)
#include <cuda_runtime.h>
#include <math.h>

#define Bz 64
#define Tn 512
#define In 256
#define Hn 1024
#define On 512
#define Gn 4096
#define NSTEPS 100

// ---------------- device scratch (static, allocation-free) ----------------
__device__ float g_h[2][Bz * Hn];
__device__ float g_c[Bz * Hn];
__device__ float g_be[Gn];
__device__ float g_bd[Gn];
__device__ float g_sd[Gn];
__device__ float g_tokf[Bz];
__device__ float g_part[4][Bz * On];

__global__ void prep_kernel(const float* __restrict__ ebih, const float* __restrict__ ebhh,
                            const float* __restrict__ dbih, const float* __restrict__ dbhh,
                            const float* __restrict__ dWih) {
    int i = blockIdx.x * blockDim.x + threadIdx.x;
    if (i < Gn) {
        g_be[i] = ebih[i] + ebhh[i];
        g_bd[i] = dbih[i] + dbhh[i];
        float s = 0.f;
        const float* row = dWih + (size_t)i * On;
        #pragma unroll 8
        for (int j = 0; j < On; j++) s += row[j];
        g_sd[i] = s;
    }
    if (i < Bz * Hn) { g_h[0][i] = 0.f; g_c[i] = 0.f; }
    if (i < Bz) g_tokf[i] = 0.f;
}

__device__ __forceinline__ float sigf(float x) { return 1.f / (1.f + expf(-x)); }

// Fused LSTM step (verified vs CPU reference, Linf ~1e-7):
// block = 64 batch rows x 32 gate cols (4 gates x 8 h-cols), grid = 128 blocks.
template <bool ENC>
__global__ __launch_bounds__(256) void lstm_step(const float* __restrict__ Wih,
                                                 const float* __restrict__ xbase,
                                                 const float* __restrict__ Whh,
                                                 int insel) {
    __shared__ float As[64 * 36];
    __shared__ float Ws[32 * 33];
    __shared__ float Gs[64 * 33];

    const int tid = threadIdx.x;
    const int tx = tid & 15;
    const int ty = tid >> 4;
    const int col_base = blockIdx.x * 8;

    float acc[4][2] = {};
    const float* hin = g_h[insel];

    for (int seg = ENC ? 0 : 1; seg < 2; ++seg) {
        const float* A;
        const float* W;
        long arst;
        int kdim;
        if (seg == 0) { A = xbase; arst = (long)Tn * In; W = Wih; kdim = In; }
        else          { A = hin;   arst = Hn;            W = Whh; kdim = Hn; }

        for (int k0 = 0; k0 < kdim; k0 += 32) {
            {   // stage A tile 64x32
                int row = tid >> 2;
                int c0 = (tid & 3) * 8;
                const float* src = A + (size_t)row * arst + k0 + c0;
                float4 v0 = *(const float4*)(src);
                float4 v1 = *(const float4*)(src + 4);
                *(float4*)&As[row * 36 + c0]     = v0;
                *(float4*)&As[row * 36 + c0 + 4] = v1;
            }
            {   // stage W tile 32x32 (the 32 gate rows this block owns)
                int wrow = tid >> 3;
                int wc = (tid & 7) * 4;
                int gr = (wrow >> 3) * Hn + col_base + (wrow & 7);
                const float* src = W + (size_t)gr * kdim + k0 + wc;
                float4 v = *(const float4*)src;
                Ws[wrow * 33 + wc + 0] = v.x;
                Ws[wrow * 33 + wc + 1] = v.y;
                Ws[wrow * 33 + wc + 2] = v.z;
                Ws[wrow * 33 + wc + 3] = v.w;
            }
            __syncthreads();
            #pragma unroll
            for (int kk = 0; kk < 32; ++kk) {
                float a0 = As[(ty * 4 + 0) * 36 + kk];
                float a1 = As[(ty * 4 + 1) * 36 + kk];
                float a2 = As[(ty * 4 + 2) * 36 + kk];
                float a3 = As[(ty * 4 + 3) * 36 + kk];
                float b0 = Ws[(tx * 2 + 0) * 33 + kk];
                float b1 = Ws[(tx * 2 + 1) * 33 + kk];
                acc[0][0] += a0 * b0; acc[0][1] += a0 * b1;
                acc[1][0] += a1 * b0; acc[1][1] += a1 * b1;
                acc[2][0] += a2 * b0; acc[2][1] += a2 * b1;
                acc[3][0] += a3 * b0; acc[3][1] += a3 * b1;
            }
            __syncthreads();
        }
    }

    #pragma unroll
    for (int i = 0; i < 4; i++) {
        int r = ty * 4 + i;
        #pragma unroll
        for (int j = 0; j < 2; j++) {
            int oc = tx * 2 + j;
            int gr = (oc >> 3) * Hn + col_base + (oc & 7);
            float g = acc[i][j] + (ENC ? g_be[gr] : g_bd[gr]);
            if (!ENC) g += g_tokf[r] * g_sd[gr];   // rank-1 token-input term
            Gs[r * 33 + oc] = g;
        }
    }
    __syncthreads();

    const int outsel = insel ^ 1;
    #pragma unroll
    for (int p0 = 0; p0 < 2; ++p0) {
        int p = tid + p0 * 256;
        int b = p >> 3;
        int hc = p & 7;
        float gi = Gs[b * 33 + hc];
        float gf = Gs[b * 33 + 8 + hc];
        float gg = Gs[b * 33 + 16 + hc];
        float go = Gs[b * 33 + 24 + hc];
        int col = col_base + hc;
        float cprev = g_c[b * Hn + col];
        float cc = sigf(gf) * cprev + sigf(gi) * tanhf(gg);
        g_c[b * Hn + col] = cc;
        g_h[outsel][b * Hn + col] = sigf(go) * tanhf(cc);
    }
}

// fc partial GEMM: grid (32 oc-tiles of 16, 4 K-quarters), 256 threads.
__global__ __launch_bounds__(256) void fc_partial(const float* __restrict__ fcW, int hsel) {
    __shared__ float Ah[64 * 36];
    __shared__ float Wf[16 * 33];
    const int tid = threadIdx.x;
    const int tx = tid & 15;   // one output col each
    const int ty = tid >> 4;   // 4 batch rows each
    const int oc0 = blockIdx.x * 16;
    const int kq = blockIdx.y;
    const float* hin = g_h[hsel];
    float acc[4] = {};

    for (int k0 = kq * 256; k0 < kq * 256 + 256; k0 += 32) {
        {
            int row = tid >> 2;
            int c0 = (tid & 3) * 8;
            const float* src = hin + (size_t)row * Hn + k0 + c0;
            *(float4*)&Ah[row * 36 + c0]     = *(const float4*)(src);
            *(float4*)&Ah[row * 36 + c0 + 4] = *(const float4*)(src + 4);
        }
        if (tid < 128) {
            int wrow = tid >> 3;
            int wc = (tid & 7) * 4;
            float4 v = *(const float4*)(fcW + (size_t)(oc0 + wrow) * Hn + k0 + wc);
            Wf[wrow * 33 + wc + 0] = v.x;
            Wf[wrow * 33 + wc + 1] = v.y;
            Wf[wrow * 33 + wc + 2] = v.z;
            Wf[wrow * 33 + wc + 3] = v.w;
        }
        __syncthreads();
        #pragma unroll
        for (int kk = 0; kk < 32; ++kk) {
            float b = Wf[tx * 33 + kk];
            acc[0] += Ah[(ty * 4 + 0) * 36 + kk] * b;
            acc[1] += Ah[(ty * 4 + 1) * 36 + kk] * b;
            acc[2] += Ah[(ty * 4 + 2) * 36 + kk] * b;
            acc[3] += Ah[(ty * 4 + 3) * 36 + kk] * b;
        }
        __syncthreads();
    }
    #pragma unroll
    for (int i = 0; i < 4; i++)
        g_part[kq][(size_t)(ty * 4 + i) * On + oc0 + tx] = acc[i];
}

// argmax per batch row, first-index tie-break (matches jnp.argmax).
// Token indices written as FLOAT32 — the harness output buffer is f32
// (reference int64 maps to float32 in the harness dtype set).
__global__ __launch_bounds__(128) void argmax_kernel(const float* __restrict__ fcb,
                                                     float* __restrict__ out, int step) {
    const int b = blockIdx.x;
    const int tid = threadIdx.x;
    __shared__ float sv[128];
    __shared__ int si[128];
    float bestv = -3.4e38f;
    int besti = 0;
    for (int o = tid; o < On; o += 128) {
        float v = fcb[o] + g_part[0][(size_t)b * On + o] + g_part[1][(size_t)b * On + o]
                         + g_part[2][(size_t)b * On + o] + g_part[3][(size_t)b * On + o];
        if (v > bestv) { bestv = v; besti = o; }   // ascending o => first index kept
    }
    sv[tid] = bestv;
    si[tid] = besti;
    __syncthreads();
    for (int s = 64; s > 0; s >>= 1) {
        if (tid < s) {
            float v2 = sv[tid + s];
            int i2 = si[tid + s];
            if (v2 > sv[tid] || (v2 == sv[tid] && i2 < si[tid])) { sv[tid] = v2; si[tid] = i2; }
        }
        __syncthreads();
    }
    if (tid == 0) {
        g_tokf[b] = (float)si[0];
        out[b * NSTEPS + step] = (float)si[0];
    }
}

extern "C" void kernel_launch(void* const* d_in, const int* in_sizes, int n_in,
                              void* d_out, int out_size) {
    // Insertion-order binding (confirmed by round-6 diagnostic):
    // [0]=inputs [1]=enc_Wih [2]=enc_Whh [3]=enc_bih [4]=enc_bhh
    // [5]=dec_Wih [6]=dec_Whh [7]=dec_bih [8]=dec_bhh [9]=fc_W [10]=fc_b
    const float* inputs  = (const float*)d_in[0];
    const float* enc_Wih = (const float*)d_in[1];
    const float* enc_Whh = (const float*)d_in[2];
    const float* enc_bih = (const float*)d_in[3];
    const float* enc_bhh = (const float*)d_in[4];
    const float* dec_Wih = (const float*)d_in[5];
    const float* dec_Whh = (const float*)d_in[6];
    const float* dec_bih = (const float*)d_in[7];
    const float* dec_bhh = (const float*)d_in[8];
    const float* fc_W    = (const float*)d_in[9];
    const float* fc_b    = (const float*)d_in[10];
    float* out = (float*)d_out;

    prep_kernel<<<256, 256>>>(enc_bih, enc_bhh, dec_bih, dec_bhh, dec_Wih);

    // encoder: 512 sequential steps; x_t rows are strided (inputs is [B, T, I])
    for (int t = 0; t < Tn; t++)
        lstm_step<true><<<128, 256>>>(enc_Wih, inputs + (size_t)t * In, enc_Whh, t & 1);

    // decoder: 100 autoregressive steps
    for (int s = 0; s < NSTEPS; s++) {
        lstm_step<false><<<128, 256>>>(nullptr, nullptr, dec_Whh, s & 1);
        fc_partial<<<dim3(32, 4), 256>>>(fc_W, (s & 1) ^ 1);
        argmax_kernel<<<64, 128>>>(fc_b, out, s);
    }
}